// round 15
// baseline (speedup 1.0000x reference)
#include <cuda_runtime.h>
#include <cstdint>

// AttentionLayer: B=2048, N=64, D=256, H=16
//   m_i[h]  = sum_d members[b,i,d]*item[b,d]*W1[d,h]
//   s[h]    = sum_i m_i[h] ; pre = 64*m_i - s + b1 ; relu ; logit = relu@W2 + b2
//   out[b,i] = softmax_i(logit)
//
// R15: occupancy push. Block = 128 thr = 4 warps = 1 batch. Warp w owns
// d-quarter [64w,64w+64); lane owns 2 heads (h0 = 2*(lane&7)) x 16 d
// (offset 16*(lane>>3) in the quarter) -> wreg = 16 ull = 32 regs, ~72 total
// -> 24 warps/SM (vs 16 in all prior rounds). NO smem ring / cp.async / TMA /
// mbarrier / syncwarp: rows stream gmem->regs via LDG.128 (8-dup coalesces to
// the same 128B lines). m/s are per-quarter partials combined in the epilogue.

constexpr int Bb = 2048;
constexpr int Nn = 64;
constexpr int Dd = 256;
constexpr int Hh = 16;
constexpr int THREADS = 128;
constexpr int MSTR = 18;               // mPart row stride (72 B, 8B-aligned)

typedef unsigned long long ull;

#define FMA2(acc, a, w)  asm("fma.rn.f32x2 %0, %1, %2, %0;" : "+l"(acc) : "l"(a), "l"(w))
#define ADD2(d, a, b_)   asm("add.rn.f32x2 %0, %1, %2;" : "=l"(d) : "l"(a), "l"(b_))
#define PACK2(d, lo, hi) asm("mov.b64 %0, {%1, %2};" : "=l"(d) : "f"(lo), "f"(hi))
#define UNPACK2(lo, hi, v) asm("mov.b64 {%0, %1}, %2;" : "=f"(lo), "=f"(hi) : "l"(v))

__global__ __launch_bounds__(THREADS, 6)
void attn_kernel(const float* __restrict__ members,
                 const float* __restrict__ item,
                 const float* __restrict__ W1,
                 const float* __restrict__ b1,
                 const float* __restrict__ W2,
                 const float* __restrict__ b2,
                 float* __restrict__ out)
{
    __shared__ float mPart[4][Nn][MSTR];   // 18.4 KB per-quarter m partials
    __shared__ float sPart[4][Hh];         // per-quarter s partials
    __shared__ float red[2][2];            // [max|sum][epilogue warp]

    const int tid  = threadIdx.x;
    const int w    = tid >> 5;             // warp -> d-quarter [64w, 64w+64)
    const int lane = tid & 31;
    const int hgrp = lane & 7;             // head pair 2*hgrp, 2*hgrp+1
    const int ds   = lane >> 3;            // 16-d slice within the quarter
    const int h0   = 2 * hgrp;
    const int b    = blockIdx.x;

    // ---- register weights: lane's 2 heads x 16 d (8 d-pairs) = 16 ull ----
    // wA[dp] = (W1[d0][h0]*it[d0], W1[d0+1][h0]*it[d0+1]);  wB: head h0+1
    const int dbase = w * 64 + ds * 16;
    const float* itG = item + (size_t)b * Dd;
    ull wA[8], wB[8];
    #pragma unroll
    for (int dp = 0; dp < 8; dp++) {
        const int d0 = dbase + 2 * dp;
        const float i0 = __ldg(&itG[d0]);
        const float i1 = __ldg(&itG[d0 + 1]);
        const float w00 = __ldg(&W1[d0 * Hh + h0]);
        const float w10 = __ldg(&W1[(d0 + 1) * Hh + h0]);
        const float w01 = __ldg(&W1[d0 * Hh + h0 + 1]);
        const float w11 = __ldg(&W1[(d0 + 1) * Hh + h0 + 1]);
        PACK2(wA[dp], w00 * i0, w10 * i1);
        PACK2(wB[dp], w01 * i0, w11 * i1);
    }

    // lane's slice of each row: 64B = 4 float4 at (b,row, dbase)
    const ulonglong2* rp =
        ((const ulonglong2*)members) + (size_t)b * (Nn * Dd / 4) + w * 16 + ds * 4;

    // ---- main loop: 32 iterations x 2 rows, zero synchronization ----
    ull sAcc = 0ull;                       // packed (s_h0, s_h1), quarter partial
    for (int i = 0; i < Nn / 2; i++) {
        ull mm[2];
        #pragma unroll
        for (int rr = 0; rr < 2; rr++) {
            const ulonglong2* rq = rp + (size_t)(2 * i + rr) * (Dd / 4);
            ull aE = 0ull, aO = 0ull, cE = 0ull, cO = 0ull;
            #pragma unroll
            for (int t = 0; t < 4; t++) {
                const ulonglong2 u = __ldg(rq + t);    // 16B of lane's 64B slice
                FMA2(aE, u.x, wA[2 * t]);
                FMA2(aO, u.y, wA[2 * t + 1]);
                FMA2(cE, u.x, wB[2 * t]);
                FMA2(cO, u.y, wB[2 * t + 1]);
            }
            ADD2(aE, aE, aO);              // head h0: (even-d, odd-d) partials
            ADD2(cE, cE, cO);              // head h0+1
            float x, y, m0, m1;
            UNPACK2(x, y, aE); m0 = x + y;
            UNPACK2(x, y, cE); m1 = x + y;
            PACK2(mm[rr], m0, m1);         // (m_h0, m_h1) quarter partial
        }

        // reduce over the 4 ds lanes (xor 8, 16); 2 independent chains
        ull tmp;
        #pragma unroll
        for (int o = 8; o <= 16; o <<= 1) {
            tmp = __shfl_xor_sync(0xffffffffu, mm[0], o); ADD2(mm[0], mm[0], tmp);
            tmp = __shfl_xor_sync(0xffffffffu, mm[1], o); ADD2(mm[1], mm[1], tmp);
        }
        ADD2(sAcc, sAcc, mm[0]);
        ADD2(sAcc, sAcc, mm[1]);

        if (ds == 0) {                     // lanes 0-7 publish 2 heads x 2 rows
            *(ull*)&mPart[w][2 * i][h0]     = mm[0];
            *(ull*)&mPart[w][2 * i + 1][h0] = mm[1];
        }
    }
    if (ds == 0) *(ull*)&sPart[w][h0] = sAcc;
    __syncthreads();                       // barrier #1: all partials visible

    // ---- epilogue: threads 0..63 handle one row each; all threads barrier ----
    const int row = tid & 63;
    const int p   = tid >> 5;              // epilogue warp parity (0/1 used)
    float logit = 0.f, e = 0.f;
    if (tid < 64) {
        logit = __ldg(b2);
        #pragma unroll
        for (int hh = 0; hh < Hh; hh++) {
            const float mv = mPart[0][row][hh] + mPart[1][row][hh]
                           + mPart[2][row][hh] + mPart[3][row][hh];
            const float sv = sPart[0][hh] + sPart[1][hh]
                           + sPart[2][hh] + sPart[3][hh];
            const float pre = 64.f * mv - sv + __ldg(&b1[hh]);
            logit += fmaxf(pre, 0.f) * __ldg(&W2[hh]);
        }
        float mx = logit;
        #pragma unroll
        for (int o = 16; o >= 1; o >>= 1)
            mx = fmaxf(mx, __shfl_xor_sync(0xffffffffu, mx, o));
        if (lane == 0) red[0][p] = mx;
    }
    __syncthreads();                       // barrier #2
    if (tid < 64) {
        const float mxAll = fmaxf(red[0][0], red[0][1]);
        e = __expf(logit - mxAll);
        float sm = e;
        #pragma unroll
        for (int o = 16; o >= 1; o >>= 1)
            sm += __shfl_xor_sync(0xffffffffu, sm, o);
        if (lane == 0) red[1][p] = sm;
    }
    __syncthreads();                       // barrier #3
    if (tid < 64) {
        const float inv = 1.0f / (red[1][0] + red[1][1]);
        out[(size_t)b * Nn + row] = e * inv;
    }
}

extern "C" void kernel_launch(void* const* d_in, const int* in_sizes, int n_in,
                              void* d_out, int out_size)
{
    attn_kernel<<<Bb, THREADS>>>(
        (const float*)d_in[0],   // members_embeds [2048,64,256]
        (const float*)d_in[1],   // item_embeds    [2048,256]
        (const float*)d_in[2],   // W1 [256,16]
        (const float*)d_in[3],   // b1 [16]
        (const float*)d_in[4],   // W2 [16,1]
        (const float*)d_in[5],   // b2 [1]
        (float*)d_out);          // out [2048,64]
}

// round 16
// speedup vs baseline: 1.6136x; 1.6136x over previous
#include <cuda_runtime.h>
#include <cstdint>

// AttentionLayer: B=2048, N=64, D=256, H=16
//   m_i[h]  = sum_d members[b,i,d]*item[b,d]*W1[d,h]
//   s[h]    = sum_i m_i[h] ; pre = 64*m_i - s + b1 ; relu ; logit = relu@W2 + b2
//   out[b,i] = softmax_i(logit)
//
// R16 = R15 occupancy (32-reg weights, 24 warps/SM) + R8 latency hiding
// (private per-warp cp.async ring). Block = 128 thr = 4 warps = 1 batch;
// warp w owns d-quarter [64w,64w+64); lane owns 4 heads (h0=4*(lane&3)) x
// 8 d (slice ds=lane>>2). Ring: 4 slots x 2 rows x 256B per warp, ONE
// cp.async.16 per lane per iteration, wait_group 2, no block barriers.
// m/s are per-quarter partials combined in the epilogue.

constexpr int Bb = 2048;
constexpr int Nn = 64;
constexpr int Dd = 256;
constexpr int Hh = 16;
constexpr int THREADS = 128;
constexpr int NSLOT = 4;               // ring slots per warp
constexpr int SROWS = 2;               // rows per slot (2 x 256B)
constexpr int ITERS = Nn / SROWS;      // 32
constexpr int MSTR = 18;               // mPart row stride (72 B, 8B-aligned)

typedef unsigned long long ull;

#define FMA2(acc, a, w)  asm("fma.rn.f32x2 %0, %1, %2, %0;" : "+l"(acc) : "l"(a), "l"(w))
#define ADD2(d, a, b_)   asm("add.rn.f32x2 %0, %1, %2;" : "=l"(d) : "l"(a), "l"(b_))
#define PACK2(d, lo, hi) asm("mov.b64 %0, {%1, %2};" : "=l"(d) : "f"(lo), "f"(hi))
#define UNPACK2(lo, hi, v) asm("mov.b64 {%0, %1}, %2;" : "=f"(lo), "=f"(hi) : "l"(v))

__device__ __forceinline__ uint32_t smem_u32(const void* p) {
    uint32_t a;
    asm("{ .reg .u64 t; cvta.to.shared.u64 t, %1; cvt.u32.u64 %0, t; }"
        : "=r"(a) : "l"(p));
    return a;
}
__device__ __forceinline__ void cp_async16(uint32_t dst, const void* src) {
    asm volatile("cp.async.cg.shared.global [%0], [%1], 16;" :: "r"(dst), "l"(src));
}
__device__ __forceinline__ void cp_commit() {
    asm volatile("cp.async.commit_group;" ::: "memory");
}
__device__ __forceinline__ void cp_wait2() {
    asm volatile("cp.async.wait_group %0;" :: "n"(NSLOT - 2) : "memory");
}

__global__ __launch_bounds__(THREADS, 6)
void attn_kernel(const float* __restrict__ members,
                 const float* __restrict__ item,
                 const float* __restrict__ W1,
                 const float* __restrict__ b1,
                 const float* __restrict__ W2,
                 const float* __restrict__ b2,
                 float* __restrict__ out)
{
    __shared__ float4 ring[4][NSLOT][SROWS][16];  // 8 KB: per-warp 4x2x256B
    __shared__ float  mPart[4][Nn][MSTR];         // 18.4 KB per-quarter m partials
    __shared__ float  sPart[4][Hh];
    __shared__ float  red[2][2];                  // [max|sum][epilogue warp]

    const int tid  = threadIdx.x;
    const int w    = tid >> 5;             // warp -> d-quarter [64w, 64w+64)
    const int lane = tid & 31;
    const int hgrp = lane & 3;             // head group -> heads 4hgrp..4hgrp+3
    const int ds   = lane >> 2;            // 8-d slice within the quarter
    const int h0   = 4 * hgrp;
    const int b    = blockIdx.x;

    // warp's quarter-row base (floats)
    const float* gq = members + (size_t)b * Nn * Dd + w * 64;
    const uint32_t ringBase = smem_u32(&ring[w][0][0][0]);
    // fill: lane covers one 16B chunk: row fr = lane>>4, chunk fc = lane&15
    const int fr = lane >> 4;
    const int fc = lane & 15;
    const uint32_t fillOff = (uint32_t)lane * 16;   // fr*256 + fc*16

    // ---- prologue: slots 0..2 (rows 0..5) in flight, 1 group each ----
    #pragma unroll
    for (int it = 0; it < NSLOT - 1; it++) {
        cp_async16(ringBase + it * 512 + fillOff,
                   gq + (2 * it + fr) * Dd + fc * 4);
        cp_commit();
    }

    // ---- register weights: lane's 4 heads x 8 d (4 d-pairs) = 16 ull ----
    // wreg[4*dp + j] = (W1[d0][h0+j]*it[d0], W1[d0+1][h0+j]*it[d0+1])
    const int dbase = w * 64 + ds * 8;
    const float* itG = item + (size_t)b * Dd;
    ull wreg[16];
    #pragma unroll
    for (int dp = 0; dp < 4; dp++) {
        const int d0 = dbase + 2 * dp;
        const float i0 = __ldg(&itG[d0]);
        const float i1 = __ldg(&itG[d0 + 1]);
        const float4 wA = __ldg((const float4*)&W1[d0 * Hh + h0]);
        const float4 wB = __ldg((const float4*)&W1[(d0 + 1) * Hh + h0]);
        PACK2(wreg[4 * dp + 0], wA.x * i0, wB.x * i1);
        PACK2(wreg[4 * dp + 1], wA.y * i0, wB.y * i1);
        PACK2(wreg[4 * dp + 2], wA.z * i0, wB.z * i1);
        PACK2(wreg[4 * dp + 3], wA.w * i0, wB.w * i1);
    }

    // ---- main loop: 32 iterations x 2 rows, no block barriers ----
    ull sA0 = 0ull, sA1 = 0ull;            // (s_h0,s_h1),(s_h2,s_h3) partials
    for (int i = 0; i < ITERS; i++) {
        cp_wait2();                 // slot i&3 landed (<=2 newer groups pending)
        __syncwarp();               // all lanes' fills of slot i visible

        const int s = i & (NSLOT - 1);
        ull mm[SROWS][2];                  // [row][(h0,h1)|(h2,h3)]
        #pragma unroll
        for (int rr = 0; rr < SROWS; rr++) {
            const ulonglong2* rp = (const ulonglong2*)&ring[w][s][rr][0];
            const ulonglong2 u0 = rp[2 * ds];      // lane's 32B: d0..d3
            const ulonglong2 u1 = rp[2 * ds + 1];  // d4..d7 (4-way bcast)
            ull a0 = 0ull, a1 = 0ull, a2 = 0ull, a3 = 0ull;
            FMA2(a0, u0.x, wreg[0]);  FMA2(a1, u0.x, wreg[1]);
            FMA2(a2, u0.x, wreg[2]);  FMA2(a3, u0.x, wreg[3]);
            FMA2(a0, u0.y, wreg[4]);  FMA2(a1, u0.y, wreg[5]);
            FMA2(a2, u0.y, wreg[6]);  FMA2(a3, u0.y, wreg[7]);
            FMA2(a0, u1.x, wreg[8]);  FMA2(a1, u1.x, wreg[9]);
            FMA2(a2, u1.x, wreg[10]); FMA2(a3, u1.x, wreg[11]);
            FMA2(a0, u1.y, wreg[12]); FMA2(a1, u1.y, wreg[13]);
            FMA2(a2, u1.y, wreg[14]); FMA2(a3, u1.y, wreg[15]);
            float x, y, m0, m1, m2, m3;
            UNPACK2(x, y, a0); m0 = x + y;
            UNPACK2(x, y, a1); m1 = x + y;
            UNPACK2(x, y, a2); m2 = x + y;
            UNPACK2(x, y, a3); m3 = x + y;
            PACK2(mm[rr][0], m0, m1);
            PACK2(mm[rr][1], m2, m3);
        }

        // 4 independent 3-level butterflies over the 8 ds lanes (xor 4,8,16)
        ull tmp;
        #pragma unroll
        for (int o = 4; o <= 16; o <<= 1) {
            tmp = __shfl_xor_sync(0xffffffffu, mm[0][0], o); ADD2(mm[0][0], mm[0][0], tmp);
            tmp = __shfl_xor_sync(0xffffffffu, mm[0][1], o); ADD2(mm[0][1], mm[0][1], tmp);
            tmp = __shfl_xor_sync(0xffffffffu, mm[1][0], o); ADD2(mm[1][0], mm[1][0], tmp);
            tmp = __shfl_xor_sync(0xffffffffu, mm[1][1], o); ADD2(mm[1][1], mm[1][1], tmp);
        }
        ADD2(sA0, sA0, mm[0][0]);  ADD2(sA0, sA0, mm[1][0]);
        ADD2(sA1, sA1, mm[0][1]);  ADD2(sA1, sA1, mm[1][1]);

        if (lane < 4) {             // ds==0 lanes publish 4 heads x 2 rows
            *(ull*)&mPart[w][2 * i][h0]         = mm[0][0];
            *(ull*)&mPart[w][2 * i][h0 + 2]     = mm[0][1];
            *(ull*)&mPart[w][2 * i + 1][h0]     = mm[1][0];
            *(ull*)&mPart[w][2 * i + 1][h0 + 2] = mm[1][1];
        }

        // refill slot (i+3)&3 (its previous contents were read last iteration)
        if (i + NSLOT - 1 < ITERS) {
            const int it = i + NSLOT - 1;
            cp_async16(ringBase + (it & (NSLOT - 1)) * 512 + fillOff,
                       gq + (2 * it + fr) * Dd + fc * 4);
        }
        cp_commit();                // unconditional: wait arithmetic stays exact
    }

    if (lane < 4) {                 // quarter s partials
        *(ull*)&sPart[w][h0]     = sA0;
        *(ull*)&sPart[w][h0 + 2] = sA1;
    }
    __syncthreads();                // barrier #1: all partials visible

    // ---- epilogue: threads 0..63 handle one row each ----
    const int row = tid & 63;
    const int p   = tid >> 5;       // epilogue warp parity (0/1 used)
    float logit = 0.f, e = 0.f;
    if (tid < 64) {
        logit = __ldg(b2);
        #pragma unroll
        for (int hh = 0; hh < Hh; hh++) {
            const float mv = mPart[0][row][hh] + mPart[1][row][hh]
                           + mPart[2][row][hh] + mPart[3][row][hh];
            const float sv = sPart[0][hh] + sPart[1][hh]
                           + sPart[2][hh] + sPart[3][hh];
            const float pre = 64.f * mv - sv + __ldg(&b1[hh]);
            logit += fmaxf(pre, 0.f) * __ldg(&W2[hh]);
        }
        float mx = logit;
        #pragma unroll
        for (int o = 16; o >= 1; o >>= 1)
            mx = fmaxf(mx, __shfl_xor_sync(0xffffffffu, mx, o));
        if ((tid & 31) == 0) red[0][p] = mx;
    }
    __syncthreads();                // barrier #2
    if (tid < 64) {
        const float mxAll = fmaxf(red[0][0], red[0][1]);
        e = __expf(logit - mxAll);
        float sm = e;
        #pragma unroll
        for (int o = 16; o >= 1; o >>= 1)
            sm += __shfl_xor_sync(0xffffffffu, sm, o);
        if ((tid & 31) == 0) red[1][p] = sm;
    }
    __syncthreads();                // barrier #3
    if (tid < 64) {
        const float inv = 1.0f / (red[1][0] + red[1][1]);
        out[(size_t)b * Nn + row] = e * inv;
    }
}

extern "C" void kernel_launch(void* const* d_in, const int* in_sizes, int n_in,
                              void* d_out, int out_size)
{
    attn_kernel<<<Bb, THREADS>>>(
        (const float*)d_in[0],   // members_embeds [2048,64,256]
        (const float*)d_in[1],   // item_embeds    [2048,256]
        (const float*)d_in[2],   // W1 [256,16]
        (const float*)d_in[3],   // b1 [16]
        (const float*)d_in[4],   // W2 [16,1]
        (const float*)d_in[5],   // b2 [1]
        (float*)d_out);          // out [2048,64]
}

// round 17
// speedup vs baseline: 1.6291x; 1.0096x over previous
#include <cuda_runtime.h>
#include <cstdint>

// AttentionLayer: B=2048, N=64, D=256, H=16
//   m_i[h]  = sum_d members[b,i,d]*item[b,d]*W1[d,h]
//   s[h]    = sum_i m_i[h] ; pre = 64*m_i - s + b1 ; relu ; logit = relu@W2 + b2
//   out[b,i] = softmax_i(logit)
//
// R16 = R15 occupancy (32-reg weights, 24 warps/SM) + R8 latency hiding
// (private per-warp cp.async ring). Block = 128 thr = 4 warps = 1 batch;
// warp w owns d-quarter [64w,64w+64); lane owns 4 heads (h0=4*(lane&3)) x
// 8 d (slice ds=lane>>2). Ring: 4 slots x 2 rows x 256B per warp, ONE
// cp.async.16 per lane per iteration, wait_group 2, no block barriers.
// m/s are per-quarter partials combined in the epilogue.

constexpr int Bb = 2048;
constexpr int Nn = 64;
constexpr int Dd = 256;
constexpr int Hh = 16;
constexpr int THREADS = 128;
constexpr int NSLOT = 4;               // ring slots per warp
constexpr int SROWS = 2;               // rows per slot (2 x 256B)
constexpr int ITERS = Nn / SROWS;      // 32
constexpr int MSTR = 18;               // mPart row stride (72 B, 8B-aligned)

typedef unsigned long long ull;

#define FMA2(acc, a, w)  asm("fma.rn.f32x2 %0, %1, %2, %0;" : "+l"(acc) : "l"(a), "l"(w))
#define ADD2(d, a, b_)   asm("add.rn.f32x2 %0, %1, %2;" : "=l"(d) : "l"(a), "l"(b_))
#define PACK2(d, lo, hi) asm("mov.b64 %0, {%1, %2};" : "=l"(d) : "f"(lo), "f"(hi))
#define UNPACK2(lo, hi, v) asm("mov.b64 {%0, %1}, %2;" : "=f"(lo), "=f"(hi) : "l"(v))

__device__ __forceinline__ uint32_t smem_u32(const void* p) {
    uint32_t a;
    asm("{ .reg .u64 t; cvta.to.shared.u64 t, %1; cvt.u32.u64 %0, t; }"
        : "=r"(a) : "l"(p));
    return a;
}
__device__ __forceinline__ void cp_async16(uint32_t dst, const void* src) {
    asm volatile("cp.async.cg.shared.global [%0], [%1], 16;" :: "r"(dst), "l"(src));
}
__device__ __forceinline__ void cp_commit() {
    asm volatile("cp.async.commit_group;" ::: "memory");
}
__device__ __forceinline__ void cp_wait2() {
    asm volatile("cp.async.wait_group %0;" :: "n"(NSLOT - 2) : "memory");
}

__global__ __launch_bounds__(THREADS, 6)
void attn_kernel(const float* __restrict__ members,
                 const float* __restrict__ item,
                 const float* __restrict__ W1,
                 const float* __restrict__ b1,
                 const float* __restrict__ W2,
                 const float* __restrict__ b2,
                 float* __restrict__ out)
{
    __shared__ float4 ring[4][NSLOT][SROWS][16];  // 8 KB: per-warp 4x2x256B
    __shared__ float  mPart[4][Nn][MSTR];         // 18.4 KB per-quarter m partials
    __shared__ float  sPart[4][Hh];
    __shared__ float  red[2][2];                  // [max|sum][epilogue warp]

    const int tid  = threadIdx.x;
    const int w    = tid >> 5;             // warp -> d-quarter [64w, 64w+64)
    const int lane = tid & 31;
    const int hgrp = lane & 3;             // head group -> heads 4hgrp..4hgrp+3
    const int ds   = lane >> 2;            // 8-d slice within the quarter
    const int h0   = 4 * hgrp;
    const int b    = blockIdx.x;

    // warp's quarter-row base (floats)
    const float* gq = members + (size_t)b * Nn * Dd + w * 64;
    const uint32_t ringBase = smem_u32(&ring[w][0][0][0]);
    // fill: lane covers one 16B chunk: row fr = lane>>4, chunk fc = lane&15
    const int fr = lane >> 4;
    const int fc = lane & 15;
    const uint32_t fillOff = (uint32_t)lane * 16;   // fr*256 + fc*16

    // ---- prologue: slots 0..2 (rows 0..5) in flight, 1 group each ----
    #pragma unroll
    for (int it = 0; it < NSLOT - 1; it++) {
        cp_async16(ringBase + it * 512 + fillOff,
                   gq + (2 * it + fr) * Dd + fc * 4);
        cp_commit();
    }

    // ---- register weights: lane's 4 heads x 8 d (4 d-pairs) = 16 ull ----
    // wreg[4*dp + j] = (W1[d0][h0+j]*it[d0], W1[d0+1][h0+j]*it[d0+1])
    const int dbase = w * 64 + ds * 8;
    const float* itG = item + (size_t)b * Dd;
    ull wreg[16];
    #pragma unroll
    for (int dp = 0; dp < 4; dp++) {
        const int d0 = dbase + 2 * dp;
        const float i0 = __ldg(&itG[d0]);
        const float i1 = __ldg(&itG[d0 + 1]);
        const float4 wA = __ldg((const float4*)&W1[d0 * Hh + h0]);
        const float4 wB = __ldg((const float4*)&W1[(d0 + 1) * Hh + h0]);
        PACK2(wreg[4 * dp + 0], wA.x * i0, wB.x * i1);
        PACK2(wreg[4 * dp + 1], wA.y * i0, wB.y * i1);
        PACK2(wreg[4 * dp + 2], wA.z * i0, wB.z * i1);
        PACK2(wreg[4 * dp + 3], wA.w * i0, wB.w * i1);
    }

    // ---- main loop: 32 iterations x 2 rows, no block barriers ----
    ull sA0 = 0ull, sA1 = 0ull;            // (s_h0,s_h1),(s_h2,s_h3) partials
    for (int i = 0; i < ITERS; i++) {
        cp_wait2();                 // slot i&3 landed (<=2 newer groups pending)
        __syncwarp();               // all lanes' fills of slot i visible

        const int s = i & (NSLOT - 1);
        ull mm[SROWS][2];                  // [row][(h0,h1)|(h2,h3)]
        #pragma unroll
        for (int rr = 0; rr < SROWS; rr++) {
            const ulonglong2* rp = (const ulonglong2*)&ring[w][s][rr][0];
            const ulonglong2 u0 = rp[2 * ds];      // lane's 32B: d0..d3
            const ulonglong2 u1 = rp[2 * ds + 1];  // d4..d7 (4-way bcast)
            ull a0 = 0ull, a1 = 0ull, a2 = 0ull, a3 = 0ull;
            FMA2(a0, u0.x, wreg[0]);  FMA2(a1, u0.x, wreg[1]);
            FMA2(a2, u0.x, wreg[2]);  FMA2(a3, u0.x, wreg[3]);
            FMA2(a0, u0.y, wreg[4]);  FMA2(a1, u0.y, wreg[5]);
            FMA2(a2, u0.y, wreg[6]);  FMA2(a3, u0.y, wreg[7]);
            FMA2(a0, u1.x, wreg[8]);  FMA2(a1, u1.x, wreg[9]);
            FMA2(a2, u1.x, wreg[10]); FMA2(a3, u1.x, wreg[11]);
            FMA2(a0, u1.y, wreg[12]); FMA2(a1, u1.y, wreg[13]);
            FMA2(a2, u1.y, wreg[14]); FMA2(a3, u1.y, wreg[15]);
            float x, y, m0, m1, m2, m3;
            UNPACK2(x, y, a0); m0 = x + y;
            UNPACK2(x, y, a1); m1 = x + y;
            UNPACK2(x, y, a2); m2 = x + y;
            UNPACK2(x, y, a3); m3 = x + y;
            PACK2(mm[rr][0], m0, m1);
            PACK2(mm[rr][1], m2, m3);
        }

        // 4 independent 3-level butterflies over the 8 ds lanes (xor 4,8,16)
        ull tmp;
        #pragma unroll
        for (int o = 4; o <= 16; o <<= 1) {
            tmp = __shfl_xor_sync(0xffffffffu, mm[0][0], o); ADD2(mm[0][0], mm[0][0], tmp);
            tmp = __shfl_xor_sync(0xffffffffu, mm[0][1], o); ADD2(mm[0][1], mm[0][1], tmp);
            tmp = __shfl_xor_sync(0xffffffffu, mm[1][0], o); ADD2(mm[1][0], mm[1][0], tmp);
            tmp = __shfl_xor_sync(0xffffffffu, mm[1][1], o); ADD2(mm[1][1], mm[1][1], tmp);
        }
        ADD2(sA0, sA0, mm[0][0]);  ADD2(sA0, sA0, mm[1][0]);
        ADD2(sA1, sA1, mm[0][1]);  ADD2(sA1, sA1, mm[1][1]);

        if (lane < 4) {             // ds==0 lanes publish 4 heads x 2 rows
            *(ull*)&mPart[w][2 * i][h0]         = mm[0][0];
            *(ull*)&mPart[w][2 * i][h0 + 2]     = mm[0][1];
            *(ull*)&mPart[w][2 * i + 1][h0]     = mm[1][0];
            *(ull*)&mPart[w][2 * i + 1][h0 + 2] = mm[1][1];
        }

        // refill slot (i+3)&3 (its previous contents were read last iteration)
        if (i + NSLOT - 1 < ITERS) {
            const int it = i + NSLOT - 1;
            cp_async16(ringBase + (it & (NSLOT - 1)) * 512 + fillOff,
                       gq + (2 * it + fr) * Dd + fc * 4);
        }
        cp_commit();                // unconditional: wait arithmetic stays exact
    }

    if (lane < 4) {                 // quarter s partials
        *(ull*)&sPart[w][h0]     = sA0;
        *(ull*)&sPart[w][h0 + 2] = sA1;
    }
    __syncthreads();                // barrier #1: all partials visible

    // ---- epilogue: threads 0..63 handle one row each ----
    const int row = tid & 63;
    const int p   = tid >> 5;       // epilogue warp parity (0/1 used)
    float logit = 0.f, e = 0.f;
    if (tid < 64) {
        logit = __ldg(b2);
        #pragma unroll
        for (int hh = 0; hh < Hh; hh++) {
            const float mv = mPart[0][row][hh] + mPart[1][row][hh]
                           + mPart[2][row][hh] + mPart[3][row][hh];
            const float sv = sPart[0][hh] + sPart[1][hh]
                           + sPart[2][hh] + sPart[3][hh];
            const float pre = 64.f * mv - sv + __ldg(&b1[hh]);
            logit += fmaxf(pre, 0.f) * __ldg(&W2[hh]);
        }
        float mx = logit;
        #pragma unroll
        for (int o = 16; o >= 1; o >>= 1)
            mx = fmaxf(mx, __shfl_xor_sync(0xffffffffu, mx, o));
        if ((tid & 31) == 0) red[0][p] = mx;
    }
    __syncthreads();                // barrier #2
    if (tid < 64) {
        const float mxAll = fmaxf(red[0][0], red[0][1]);
        e = __expf(logit - mxAll);
        float sm = e;
        #pragma unroll
        for (int o = 16; o >= 1; o >>= 1)
            sm += __shfl_xor_sync(0xffffffffu, sm, o);
        if ((tid & 31) == 0) red[1][p] = sm;
    }
    __syncthreads();                // barrier #3
    if (tid < 64) {
        const float inv = 1.0f / (red[1][0] + red[1][1]);
        out[(size_t)b * Nn + row] = e * inv;
    }
}

extern "C" void kernel_launch(void* const* d_in, const int* in_sizes, int n_in,
                              void* d_out, int out_size)
{
    attn_kernel<<<Bb, THREADS>>>(
        (const float*)d_in[0],   // members_embeds [2048,64,256]
        (const float*)d_in[1],   // item_embeds    [2048,256]
        (const float*)d_in[2],   // W1 [256,16]
        (const float*)d_in[3],   // b1 [16]
        (const float*)d_in[4],   // W2 [16,1]
        (const float*)d_in[5],   // b2 [1]
        (float*)d_out);          // out [2048,64]
}